// round 5
// baseline (speedup 1.0000x reference)
#include <cuda_runtime.h>
#include <cuda_fp16.h>
#include <cstdint>

#define DHID   128
#define NB     4
#define NN_MAX 100096
#define NE_MAX 800000
#define NBKT_N 102400          // 1024 * 100, >= NN_MAX, per-node buckets
#define SCAN_ITEMS (NBKT_N / 1024)

// Scratch
__device__ __half   g_xb[(size_t)NN_MAX * NB * DHID];   // fp16 basis projections
__device__ __half   g_wt[NB * DHID * DHID];             // transposed fp16 weights
__device__ uint32_t g_hist[NBKT_N];                     // per-dst counts -> cursors
__device__ uint2    g_edges2[NE_MAX];                   // dst-sorted {src|rel<<20, norm}

#define KP 136  // smem row pitch in fp16

// ---------------------------------------------------------------------------
// Prep: weight[b][k][o] fp32 -> g_wt[b][o][k] fp16
// ---------------------------------------------------------------------------
__global__ void rgcn_prep_w(const float* __restrict__ weight)
{
    int idx = blockIdx.x * blockDim.x + threadIdx.x;
    if (idx >= NB * DHID * DHID) return;
    int b = idx >> 14;
    int k = (idx >> 7) & 127;
    int o = idx & 127;
    g_wt[(b * DHID + o) * DHID + k] = __float2half_rn(weight[idx]);
}

// ---------------------------------------------------------------------------
// Init: zero histogram
// ---------------------------------------------------------------------------
__global__ void rgcn_init_kernel()
{
    int i = blockIdx.x * blockDim.x + threadIdx.x;
    if (i < NBKT_N) g_hist[i] = 0u;
}

// ---------------------------------------------------------------------------
// Sort pass 1: per-dst histogram
// ---------------------------------------------------------------------------
__global__ void rgcn_hist_kernel(const int* __restrict__ dst, int n_edges)
{
    int e = blockIdx.x * blockDim.x + threadIdx.x;
    if (e >= n_edges) return;
    atomicAdd(&g_hist[(unsigned)dst[e]], 1u);
}

// ---------------------------------------------------------------------------
// Sort pass 2: exclusive scan (single block, 1024 threads, 2-pass per thread)
// ---------------------------------------------------------------------------
__global__ __launch_bounds__(1024) void rgcn_scan_kernel()
{
    __shared__ uint32_t part[1024];
    const int t = threadIdx.x;
    const int base = t * SCAN_ITEMS;
    uint32_t s = 0;
    for (int i = 0; i < SCAN_ITEMS; ++i) s += g_hist[base + i];
    part[t] = s;
    __syncthreads();
    for (int off = 1; off < 1024; off <<= 1) {
        uint32_t v = (t >= off) ? part[t - off] : 0u;
        __syncthreads();
        part[t] += v;
        __syncthreads();
    }
    uint32_t ex = (t > 0) ? part[t - 1] : 0u;
    for (int i = 0; i < SCAN_ITEMS; ++i) {
        uint32_t v = g_hist[base + i];
        g_hist[base + i] = ex;
        ex += v;
    }
}

// ---------------------------------------------------------------------------
// Sort pass 3: scatter edges into dst order (8B records)
// After this pass g_hist[d] = end offset of bucket d (inclusive prefix).
// ---------------------------------------------------------------------------
__global__ void rgcn_scatter_kernel(
    const int*   __restrict__ r,
    const float* __restrict__ norm,
    const int*   __restrict__ src,
    const int*   __restrict__ dst,
    int n_edges)
{
    int e = blockIdx.x * blockDim.x + threadIdx.x;
    if (e >= n_edges) return;
    uint32_t pos = atomicAdd(&g_hist[(unsigned)dst[e]], 1u);
    uint2 ed;
    ed.x = (unsigned)src[e] | ((unsigned)r[e] << 20);
    ed.y = __float_as_uint(norm[e]);
    g_edges2[pos] = ed;
}

// ---------------------------------------------------------------------------
// GEMM: block = 128 nodes x 512 outputs (4 bases x 128), HMMA m16n8k16.
// ---------------------------------------------------------------------------
__device__ __forceinline__ uint32_t smem_u32(const void* p) {
    uint32_t a;
    asm("{ .reg .u64 t; cvta.to.shared.u64 t, %1; cvt.u32.u64 %0, t; }" : "=r"(a) : "l"(p));
    return a;
}
__device__ __forceinline__ void ldsm_x4(uint32_t* r, uint32_t addr) {
    asm volatile("ldmatrix.sync.aligned.m8n8.x4.shared.b16 {%0,%1,%2,%3}, [%4];"
                 : "=r"(r[0]), "=r"(r[1]), "=r"(r[2]), "=r"(r[3]) : "r"(addr));
}
__device__ __forceinline__ void ldsm_x2(uint32_t* r, uint32_t addr) {
    asm volatile("ldmatrix.sync.aligned.m8n8.x2.shared.b16 {%0,%1}, [%2];"
                 : "=r"(r[0]), "=r"(r[1]) : "r"(addr));
}
__device__ __forceinline__ void mma16816(float* c, const uint32_t* a, const uint32_t* b) {
    asm volatile(
        "mma.sync.aligned.m16n8k16.row.col.f32.f16.f16.f32 "
        "{%0,%1,%2,%3}, {%4,%5,%6,%7}, {%8,%9}, {%0,%1,%2,%3};"
        : "+f"(c[0]), "+f"(c[1]), "+f"(c[2]), "+f"(c[3])
        : "r"(a[0]), "r"(a[1]), "r"(a[2]), "r"(a[3]), "r"(b[0]), "r"(b[1]));
}

#define SMEM_BYTES ((128 * KP * 2) * 2)

__global__ __launch_bounds__(256) void rgcn_gemm_mma(
    const int*   __restrict__ h,
    const float* __restrict__ emb,
    int n_nodes)
{
    extern __shared__ __align__(16) __half smem[];
    __half* As = smem;
    __half* Bs = smem + 128 * KP;

    const int tid  = threadIdx.x;
    const int lane = tid & 31;
    const int wrp  = tid >> 5;
    const int wm   = (wrp & 3) * 32;
    const int wn   = (wrp >> 2) * 64;
    const int m0   = blockIdx.x * 128;

    #pragma unroll
    for (int it = 0; it < 16; ++it) {
        int idx  = it * 256 + tid;
        int m    = idx >> 5;
        int kc   = (idx & 31) * 4;
        int node = m0 + m;
        float4 v = make_float4(0.f, 0.f, 0.f, 0.f);
        if (node < n_nodes) {
            int hn = __ldg(h + node);
            v = *reinterpret_cast<const float4*>(emb + (size_t)hn * DHID + kc);
        }
        __half2 p0 = __floats2half2_rn(v.x, v.y);
        __half2 p1 = __floats2half2_rn(v.z, v.w);
        uint2 pk;
        pk.x = *reinterpret_cast<uint32_t*>(&p0);
        pk.y = *reinterpret_cast<uint32_t*>(&p1);
        *reinterpret_cast<uint2*>(As + m * KP + kc) = pk;
    }

    uint32_t as_base = smem_u32(As);
    uint32_t bs_base = smem_u32(Bs);
    const int arow  = (lane & 15);
    const int acol8 = 8 * (lane >> 4);
    const int brow  = (lane & 7);
    const int bcol8 = 8 * ((lane >> 3) & 1);
    const int gq = lane >> 2;
    const int tg = lane & 3;

    for (int b = 0; b < NB; ++b) {
        __syncthreads();
        const uint4* wsrc = reinterpret_cast<const uint4*>(g_wt + b * DHID * DHID);
        #pragma unroll
        for (int it = 0; it < 8; ++it) {
            int idx = it * 256 + tid;
            int o   = idx >> 4;
            int kq  = (idx & 15) * 8;
            *reinterpret_cast<uint4*>(Bs + o * KP + kq) = wsrc[idx];
        }
        __syncthreads();

        float acc[2][8][4];
        #pragma unroll
        for (int mi = 0; mi < 2; ++mi)
            #pragma unroll
            for (int ni = 0; ni < 8; ++ni)
                #pragma unroll
                for (int q = 0; q < 4; ++q) acc[mi][ni][q] = 0.f;

        #pragma unroll
        for (int kk = 0; kk < 8; ++kk) {
            uint32_t af[2][4], bf[8][2];
            #pragma unroll
            for (int mi = 0; mi < 2; ++mi)
                ldsm_x4(af[mi], as_base + ((wm + mi * 16 + arow) * KP + kk * 16 + acol8) * 2);
            #pragma unroll
            for (int ni = 0; ni < 8; ++ni)
                ldsm_x2(bf[ni], bs_base + ((wn + ni * 8 + brow) * KP + kk * 16 + bcol8) * 2);
            #pragma unroll
            for (int mi = 0; mi < 2; ++mi)
                #pragma unroll
                for (int ni = 0; ni < 8; ++ni)
                    mma16816(acc[mi][ni], af[mi], bf[ni]);
        }

        #pragma unroll
        for (int mi = 0; mi < 2; ++mi) {
            int node0 = m0 + wm + mi * 16 + gq;
            #pragma unroll
            for (int half_ = 0; half_ < 2; ++half_) {
                int node = node0 + half_ * 8;
                if (node < n_nodes) {
                    __half* orow = g_xb + (size_t)node * (NB * DHID) + b * DHID + wn + tg * 2;
                    #pragma unroll
                    for (int ni = 0; ni < 8; ++ni) {
                        __half2 v = __floats2half2_rn(acc[mi][ni][half_ * 2],
                                                      acc[mi][ni][half_ * 2 + 1]);
                        *reinterpret_cast<__half2*>(orow + ni * 8) = v;
                    }
                }
            }
        }
    }
}

// ---------------------------------------------------------------------------
// Edge+finalize: one warp per DST node. Loop in-edges (dst-sorted), gather
// xb[src], accumulate in registers, write out = acc/deg + bias. No atomics.
// ---------------------------------------------------------------------------
__global__ __launch_bounds__(256) void rgcn_edge_kernel(
    const float* __restrict__ w_comp,
    const float* __restrict__ bias,
    float*       __restrict__ out,
    int n_nodes)
{
    int d    = blockIdx.x * 8 + (threadIdx.x >> 5);
    int lane = threadIdx.x & 31;
    if (d >= n_nodes) return;

    uint32_t end   = __ldg(&g_hist[d]);                     // inclusive prefix = bucket end
    uint32_t begin = (d > 0) ? __ldg(&g_hist[d - 1]) : 0u;  // previous end = start

    float4 acc = make_float4(0.f, 0.f, 0.f, 0.f);

    for (uint32_t e = begin; e < end; ++e) {
        uint2 ed = __ldg(&g_edges2[e]);                     // broadcast
        int   s   = (int)(ed.x & 0xFFFFFu);
        int   rel = (int)(ed.x >> 20);
        float nm  = __uint_as_float(ed.y);
        float4 c  = __ldg(reinterpret_cast<const float4*>(w_comp) + rel);

        const uint2* xp = reinterpret_cast<const uint2*>(g_xb + (size_t)s * (NB * DHID)) + lane;
        uint2 q0 = __ldg(xp);
        uint2 q1 = __ldg(xp + 32);
        uint2 q2 = __ldg(xp + 64);
        uint2 q3 = __ldg(xp + 96);

        float2 a0 = __half22float2(*reinterpret_cast<__half2*>(&q0.x));
        float2 a1 = __half22float2(*reinterpret_cast<__half2*>(&q0.y));
        float2 b0 = __half22float2(*reinterpret_cast<__half2*>(&q1.x));
        float2 b1 = __half22float2(*reinterpret_cast<__half2*>(&q1.y));
        float2 c0 = __half22float2(*reinterpret_cast<__half2*>(&q2.x));
        float2 c1 = __half22float2(*reinterpret_cast<__half2*>(&q2.y));
        float2 d0 = __half22float2(*reinterpret_cast<__half2*>(&q3.x));
        float2 d1 = __half22float2(*reinterpret_cast<__half2*>(&q3.y));

        acc.x += nm * (c.x * a0.x + c.y * b0.x + c.z * c0.x + c.w * d0.x);
        acc.y += nm * (c.x * a0.y + c.y * b0.y + c.z * c0.y + c.w * d0.y);
        acc.z += nm * (c.x * a1.x + c.y * b1.x + c.z * c1.x + c.w * d1.x);
        acc.w += nm * (c.x * a1.y + c.y * b1.y + c.z * c1.y + c.w * d1.y);
    }

    uint32_t deg = end - begin;
    float rc = (deg > 0u) ? (1.0f / (float)deg) : 1.0f;
    float4 bv = __ldg(reinterpret_cast<const float4*>(bias) + lane);
    float4 o;
    o.x = acc.x * rc + bv.x;
    o.y = acc.y * rc + bv.y;
    o.z = acc.z * rc + bv.z;
    o.w = acc.w * rc + bv.w;
    *reinterpret_cast<float4*>(out + (size_t)d * DHID + lane * 4) = o;
}

// ---------------------------------------------------------------------------
// Inputs: h, r, norm, src, dst, emb_table, weight, w_comp, h_bias
// ---------------------------------------------------------------------------
extern "C" void kernel_launch(void* const* d_in, const int* in_sizes, int n_in,
                              void* d_out, int out_size)
{
    const int*   h      = (const int*)  d_in[0];
    const int*   r      = (const int*)  d_in[1];
    const float* norm   = (const float*)d_in[2];
    const int*   src    = (const int*)  d_in[3];
    const int*   dst    = (const int*)  d_in[4];
    const float* emb    = (const float*)d_in[5];
    const float* weight = (const float*)d_in[6];
    const float* w_comp = (const float*)d_in[7];
    const float* bias   = (const float*)d_in[8];

    int n_nodes = in_sizes[0];
    int n_edges = in_sizes[1];
    float* out = (float*)d_out;

    cudaFuncSetAttribute(rgcn_gemm_mma, cudaFuncAttributeMaxDynamicSharedMemorySize, SMEM_BYTES);

    // 0) weight -> transposed fp16; zero histogram
    rgcn_prep_w<<<(NB * DHID * DHID + 255) / 256, 256>>>(weight);
    rgcn_init_kernel<<<(NBKT_N + 255) / 256, 256>>>();

    // 1) counting sort of edges by dst node
    int eblk = (n_edges + 255) / 256;
    rgcn_hist_kernel<<<eblk, 256>>>(dst, n_edges);
    rgcn_scan_kernel<<<1, 1024>>>();
    rgcn_scatter_kernel<<<eblk, 256>>>(r, norm, src, dst, n_edges);

    // 2) basis projections on tensor cores (HMMA)
    rgcn_gemm_mma<<<(n_nodes + 127) / 128, 256, SMEM_BYTES>>>(h, emb, n_nodes);

    // 3) per-dst gather + reduce + bias (no atomics, fused finalize)
    rgcn_edge_kernel<<<(n_nodes + 7) / 8, 256>>>(w_comp, bias, out, n_nodes);
}

// round 6
// speedup vs baseline: 1.4778x; 1.4778x over previous
#include <cuda_runtime.h>
#include <cuda_fp16.h>
#include <cstdint>

#define DHID   128
#define NB     4
#define NN_MAX 100096
#define NE_MAX 800000
#define NBKT_N 102400          // 100 blocks * 1024, >= NN_MAX
#define NSCAN_BLK (NBKT_N / 1024)   // 100

// Scratch
__device__ __half   g_xb[(size_t)NN_MAX * NB * DHID];   // fp16 basis projections
__device__ __half   g_wt[NB * DHID * DHID];             // transposed fp16 weights
__device__ uint32_t g_hist[NBKT_N];                     // per-dst counts -> cursors
__device__ uint32_t g_bsum[128];                        // block sums for 2-level scan
__device__ uint2    g_edges2[NE_MAX];                   // dst-sorted {src|rel<<20, norm}

#define KP 136  // smem row pitch in fp16

// ---------------------------------------------------------------------------
// Prep: weight[b][k][o] fp32 -> g_wt[b][o][k] fp16
// ---------------------------------------------------------------------------
__global__ void rgcn_prep_w(const float* __restrict__ weight)
{
    int idx = blockIdx.x * blockDim.x + threadIdx.x;
    if (idx >= NB * DHID * DHID) return;
    int b = idx >> 14;
    int k = (idx >> 7) & 127;
    int o = idx & 127;
    g_wt[(b * DHID + o) * DHID + k] = __float2half_rn(weight[idx]);
}

// ---------------------------------------------------------------------------
// Init: zero histogram
// ---------------------------------------------------------------------------
__global__ void rgcn_init_kernel()
{
    int i = blockIdx.x * blockDim.x + threadIdx.x;
    if (i < NBKT_N) g_hist[i] = 0u;
}

// ---------------------------------------------------------------------------
// Sort pass 1: per-dst histogram
// ---------------------------------------------------------------------------
__global__ void rgcn_hist_kernel(const int* __restrict__ dst, int n_edges)
{
    int e = blockIdx.x * blockDim.x + threadIdx.x;
    if (e >= n_edges) return;
    atomicAdd(&g_hist[(unsigned)dst[e]], 1u);
}

// ---------------------------------------------------------------------------
// Sort pass 2a: block-local exclusive scan (coalesced), emit block totals
// ---------------------------------------------------------------------------
__global__ __launch_bounds__(1024) void rgcn_scan_local()
{
    __shared__ uint32_t sh[1024];
    int t = threadIdx.x;
    int i = blockIdx.x * 1024 + t;
    uint32_t v = g_hist[i];
    sh[t] = v;
    __syncthreads();
    #pragma unroll
    for (int off = 1; off < 1024; off <<= 1) {
        uint32_t u = (t >= off) ? sh[t - off] : 0u;
        __syncthreads();
        sh[t] += u;
        __syncthreads();
    }
    g_hist[i] = sh[t] - v;                 // exclusive within block
    if (t == 1023) g_bsum[blockIdx.x] = sh[t];
}

// ---------------------------------------------------------------------------
// Sort pass 2b: exclusive scan of the 100 block sums (one tiny block)
// ---------------------------------------------------------------------------
__global__ __launch_bounds__(128) void rgcn_scan_bsums()
{
    __shared__ uint32_t sh[128];
    int t = threadIdx.x;
    uint32_t v = (t < NSCAN_BLK) ? g_bsum[t] : 0u;
    sh[t] = v;
    __syncthreads();
    #pragma unroll
    for (int off = 1; off < 128; off <<= 1) {
        uint32_t u = (t >= off) ? sh[t - off] : 0u;
        __syncthreads();
        sh[t] += u;
        __syncthreads();
    }
    g_bsum[t] = sh[t] - v;                 // exclusive
}

// ---------------------------------------------------------------------------
// Sort pass 2c: add block offsets -> global exclusive prefix (scatter cursors)
// ---------------------------------------------------------------------------
__global__ __launch_bounds__(1024) void rgcn_scan_add()
{
    int t = threadIdx.x;
    int i = blockIdx.x * 1024 + t;
    g_hist[i] += g_bsum[blockIdx.x];
}

// ---------------------------------------------------------------------------
// Sort pass 3: scatter edges into dst order (8B records)
// After this pass g_hist[d] = inclusive end of bucket d.
// ---------------------------------------------------------------------------
__global__ void rgcn_scatter_kernel(
    const int*   __restrict__ r,
    const float* __restrict__ norm,
    const int*   __restrict__ src,
    const int*   __restrict__ dst,
    int n_edges)
{
    int e = blockIdx.x * blockDim.x + threadIdx.x;
    if (e >= n_edges) return;
    uint32_t pos = atomicAdd(&g_hist[(unsigned)dst[e]], 1u);
    uint2 ed;
    ed.x = (unsigned)src[e] | ((unsigned)r[e] << 20);
    ed.y = __float_as_uint(norm[e]);
    g_edges2[pos] = ed;
}

// ---------------------------------------------------------------------------
// GEMM: block = 128 nodes x 512 outputs (4 bases x 128), HMMA m16n8k16.
// ---------------------------------------------------------------------------
__device__ __forceinline__ uint32_t smem_u32(const void* p) {
    uint32_t a;
    asm("{ .reg .u64 t; cvta.to.shared.u64 t, %1; cvt.u32.u64 %0, t; }" : "=r"(a) : "l"(p));
    return a;
}
__device__ __forceinline__ void ldsm_x4(uint32_t* r, uint32_t addr) {
    asm volatile("ldmatrix.sync.aligned.m8n8.x4.shared.b16 {%0,%1,%2,%3}, [%4];"
                 : "=r"(r[0]), "=r"(r[1]), "=r"(r[2]), "=r"(r[3]) : "r"(addr));
}
__device__ __forceinline__ void ldsm_x2(uint32_t* r, uint32_t addr) {
    asm volatile("ldmatrix.sync.aligned.m8n8.x2.shared.b16 {%0,%1}, [%2];"
                 : "=r"(r[0]), "=r"(r[1]) : "r"(addr));
}
__device__ __forceinline__ void mma16816(float* c, const uint32_t* a, const uint32_t* b) {
    asm volatile(
        "mma.sync.aligned.m16n8k16.row.col.f32.f16.f16.f32 "
        "{%0,%1,%2,%3}, {%4,%5,%6,%7}, {%8,%9}, {%0,%1,%2,%3};"
        : "+f"(c[0]), "+f"(c[1]), "+f"(c[2]), "+f"(c[3])
        : "r"(a[0]), "r"(a[1]), "r"(a[2]), "r"(a[3]), "r"(b[0]), "r"(b[1]));
}

#define SMEM_BYTES ((128 * KP * 2) * 2)

__global__ __launch_bounds__(256) void rgcn_gemm_mma(
    const int*   __restrict__ h,
    const float* __restrict__ emb,
    int n_nodes)
{
    extern __shared__ __align__(16) __half smem[];
    __half* As = smem;
    __half* Bs = smem + 128 * KP;

    const int tid  = threadIdx.x;
    const int lane = tid & 31;
    const int wrp  = tid >> 5;
    const int wm   = (wrp & 3) * 32;
    const int wn   = (wrp >> 2) * 64;
    const int m0   = blockIdx.x * 128;

    #pragma unroll
    for (int it = 0; it < 16; ++it) {
        int idx  = it * 256 + tid;
        int m    = idx >> 5;
        int kc   = (idx & 31) * 4;
        int node = m0 + m;
        float4 v = make_float4(0.f, 0.f, 0.f, 0.f);
        if (node < n_nodes) {
            int hn = __ldg(h + node);
            v = *reinterpret_cast<const float4*>(emb + (size_t)hn * DHID + kc);
        }
        __half2 p0 = __floats2half2_rn(v.x, v.y);
        __half2 p1 = __floats2half2_rn(v.z, v.w);
        uint2 pk;
        pk.x = *reinterpret_cast<uint32_t*>(&p0);
        pk.y = *reinterpret_cast<uint32_t*>(&p1);
        *reinterpret_cast<uint2*>(As + m * KP + kc) = pk;
    }

    uint32_t as_base = smem_u32(As);
    uint32_t bs_base = smem_u32(Bs);
    const int arow  = (lane & 15);
    const int acol8 = 8 * (lane >> 4);
    const int brow  = (lane & 7);
    const int bcol8 = 8 * ((lane >> 3) & 1);
    const int gq = lane >> 2;
    const int tg = lane & 3;

    for (int b = 0; b < NB; ++b) {
        __syncthreads();
        const uint4* wsrc = reinterpret_cast<const uint4*>(g_wt + b * DHID * DHID);
        #pragma unroll
        for (int it = 0; it < 8; ++it) {
            int idx = it * 256 + tid;
            int o   = idx >> 4;
            int kq  = (idx & 15) * 8;
            *reinterpret_cast<uint4*>(Bs + o * KP + kq) = wsrc[idx];
        }
        __syncthreads();

        float acc[2][8][4];
        #pragma unroll
        for (int mi = 0; mi < 2; ++mi)
            #pragma unroll
            for (int ni = 0; ni < 8; ++ni)
                #pragma unroll
                for (int q = 0; q < 4; ++q) acc[mi][ni][q] = 0.f;

        #pragma unroll
        for (int kk = 0; kk < 8; ++kk) {
            uint32_t af[2][4], bf[8][2];
            #pragma unroll
            for (int mi = 0; mi < 2; ++mi)
                ldsm_x4(af[mi], as_base + ((wm + mi * 16 + arow) * KP + kk * 16 + acol8) * 2);
            #pragma unroll
            for (int ni = 0; ni < 8; ++ni)
                ldsm_x2(bf[ni], bs_base + ((wn + ni * 8 + brow) * KP + kk * 16 + bcol8) * 2);
            #pragma unroll
            for (int mi = 0; mi < 2; ++mi)
                #pragma unroll
                for (int ni = 0; ni < 8; ++ni)
                    mma16816(acc[mi][ni], af[mi], bf[ni]);
        }

        #pragma unroll
        for (int mi = 0; mi < 2; ++mi) {
            int node0 = m0 + wm + mi * 16 + gq;
            #pragma unroll
            for (int half_ = 0; half_ < 2; ++half_) {
                int node = node0 + half_ * 8;
                if (node < n_nodes) {
                    __half* orow = g_xb + (size_t)node * (NB * DHID) + b * DHID + wn + tg * 2;
                    #pragma unroll
                    for (int ni = 0; ni < 8; ++ni) {
                        __half2 v = __floats2half2_rn(acc[mi][ni][half_ * 2],
                                                      acc[mi][ni][half_ * 2 + 1]);
                        *reinterpret_cast<__half2*>(orow + ni * 8) = v;
                    }
                }
            }
        }
    }
}

// ---------------------------------------------------------------------------
// Edge+finalize: one warp per DST node. Loop in-edges (dst-sorted), gather
// xb[src], accumulate in registers, write out = acc/deg + bias. No atomics.
// ---------------------------------------------------------------------------
__global__ __launch_bounds__(256) void rgcn_edge_kernel(
    const float* __restrict__ w_comp,
    const float* __restrict__ bias,
    float*       __restrict__ out,
    int n_nodes)
{
    int d    = blockIdx.x * 8 + (threadIdx.x >> 5);
    int lane = threadIdx.x & 31;
    if (d >= n_nodes) return;

    uint32_t end   = __ldg(&g_hist[d]);
    uint32_t begin = (d > 0) ? __ldg(&g_hist[d - 1]) : 0u;

    float4 acc = make_float4(0.f, 0.f, 0.f, 0.f);

    for (uint32_t e = begin; e < end; ++e) {
        uint2 ed = __ldg(&g_edges2[e]);
        int   s   = (int)(ed.x & 0xFFFFFu);
        int   rel = (int)(ed.x >> 20);
        float nm  = __uint_as_float(ed.y);
        float4 c  = __ldg(reinterpret_cast<const float4*>(w_comp) + rel);

        const uint2* xp = reinterpret_cast<const uint2*>(g_xb + (size_t)s * (NB * DHID)) + lane;
        uint2 q0 = __ldg(xp);
        uint2 q1 = __ldg(xp + 32);
        uint2 q2 = __ldg(xp + 64);
        uint2 q3 = __ldg(xp + 96);

        float2 a0 = __half22float2(*reinterpret_cast<__half2*>(&q0.x));
        float2 a1 = __half22float2(*reinterpret_cast<__half2*>(&q0.y));
        float2 b0 = __half22float2(*reinterpret_cast<__half2*>(&q1.x));
        float2 b1 = __half22float2(*reinterpret_cast<__half2*>(&q1.y));
        float2 c0 = __half22float2(*reinterpret_cast<__half2*>(&q2.x));
        float2 c1 = __half22float2(*reinterpret_cast<__half2*>(&q2.y));
        float2 d0 = __half22float2(*reinterpret_cast<__half2*>(&q3.x));
        float2 d1 = __half22float2(*reinterpret_cast<__half2*>(&q3.y));

        acc.x += nm * (c.x * a0.x + c.y * b0.x + c.z * c0.x + c.w * d0.x);
        acc.y += nm * (c.x * a0.y + c.y * b0.y + c.z * c0.y + c.w * d0.y);
        acc.z += nm * (c.x * a1.x + c.y * b1.x + c.z * c1.x + c.w * d1.x);
        acc.w += nm * (c.x * a1.y + c.y * b1.y + c.z * c1.y + c.w * d1.y);
    }

    uint32_t deg = end - begin;
    float rc = (deg > 0u) ? (1.0f / (float)deg) : 1.0f;
    float4 bv = __ldg(reinterpret_cast<const float4*>(bias) + lane);
    float4 o;
    o.x = acc.x * rc + bv.x;
    o.y = acc.y * rc + bv.y;
    o.z = acc.z * rc + bv.z;
    o.w = acc.w * rc + bv.w;
    *reinterpret_cast<float4*>(out + (size_t)d * DHID + lane * 4) = o;
}

// ---------------------------------------------------------------------------
// Inputs: h, r, norm, src, dst, emb_table, weight, w_comp, h_bias
// ---------------------------------------------------------------------------
extern "C" void kernel_launch(void* const* d_in, const int* in_sizes, int n_in,
                              void* d_out, int out_size)
{
    const int*   h      = (const int*)  d_in[0];
    const int*   r      = (const int*)  d_in[1];
    const float* norm   = (const float*)d_in[2];
    const int*   src    = (const int*)  d_in[3];
    const int*   dst    = (const int*)  d_in[4];
    const float* emb    = (const float*)d_in[5];
    const float* weight = (const float*)d_in[6];
    const float* w_comp = (const float*)d_in[7];
    const float* bias   = (const float*)d_in[8];

    int n_nodes = in_sizes[0];
    int n_edges = in_sizes[1];
    float* out = (float*)d_out;

    cudaFuncSetAttribute(rgcn_gemm_mma, cudaFuncAttributeMaxDynamicSharedMemorySize, SMEM_BYTES);

    // 0) weight -> transposed fp16; zero histogram
    rgcn_prep_w<<<(NB * DHID * DHID + 255) / 256, 256>>>(weight);
    rgcn_init_kernel<<<(NBKT_N + 255) / 256, 256>>>();

    // 1) counting sort of edges by dst node (2-level coalesced scan)
    int eblk = (n_edges + 255) / 256;
    rgcn_hist_kernel<<<eblk, 256>>>(dst, n_edges);
    rgcn_scan_local<<<NSCAN_BLK, 1024>>>();
    rgcn_scan_bsums<<<1, 128>>>();
    rgcn_scan_add<<<NSCAN_BLK, 1024>>>();
    rgcn_scatter_kernel<<<eblk, 256>>>(r, norm, src, dst, n_edges);

    // 2) basis projections on tensor cores (HMMA)
    rgcn_gemm_mma<<<(n_nodes + 127) / 128, 256, SMEM_BYTES>>>(h, emb, n_nodes);

    // 3) per-dst gather + reduce + bias (no atomics, fused finalize)
    rgcn_edge_kernel<<<(n_nodes + 7) / 8, 256>>>(w_comp, bias, out, n_nodes);
}

// round 7
// speedup vs baseline: 1.6982x; 1.1492x over previous
#include <cuda_runtime.h>
#include <cuda_fp16.h>
#include <cstdint>

#define DHID   128
#define NB     4
#define NN_MAX 100096
#define NE_MAX 800000
#define NBKT_N 102400          // 100 blocks * 1024, >= NN_MAX
#define NSCAN_BLK (NBKT_N / 1024)

// Scratch
__device__ __half   g_x[(size_t)NN_MAX * DHID];         // fp16 node feats (25.6 MB)
__device__ __half   g_y[(size_t)NN_MAX * NB * DHID];    // fp16 aggregated, deg-scaled (102 MB)
__device__ __half   g_wt2[DHID * NB * DHID];            // Wt[o][b*128+i] fp16 (128 KB)
__device__ uint32_t g_hist[NBKT_N];
__device__ uint32_t g_bsum[128];
__device__ uint2    g_edges2[NE_MAX];                   // dst-sorted {src|rel<<20, norm}

#define KP 136  // smem row pitch in fp16

// ---------------------------------------------------------------------------
// Prep: weight[b][i][o] fp32 -> g_wt2[o][b*128+i] fp16  (B^T for mma row.col)
// ---------------------------------------------------------------------------
__global__ void rgcn_prep_w(const float* __restrict__ weight)
{
    int idx = blockIdx.x * blockDim.x + threadIdx.x;
    if (idx >= NB * DHID * DHID) return;
    int b = idx >> 14;
    int i = (idx >> 7) & 127;
    int o = idx & 127;
    g_wt2[o * (NB * DHID) + b * DHID + i] = __float2half_rn(weight[idx]);
}

// ---------------------------------------------------------------------------
// Prep: x[n] = fp16(emb[h[n]])
// ---------------------------------------------------------------------------
__global__ void rgcn_prep_x(const int* __restrict__ h,
                            const float* __restrict__ emb,
                            int n_nodes)
{
    int idx = blockIdx.x * blockDim.x + threadIdx.x;
    if (idx >= n_nodes * 32) return;
    int n  = idx >> 5;
    int qc = (idx & 31) * 4;
    int hn = __ldg(h + n);
    float4 v = *reinterpret_cast<const float4*>(emb + (size_t)hn * DHID + qc);
    __half2 p0 = __floats2half2_rn(v.x, v.y);
    __half2 p1 = __floats2half2_rn(v.z, v.w);
    uint2 pk;
    pk.x = *reinterpret_cast<uint32_t*>(&p0);
    pk.y = *reinterpret_cast<uint32_t*>(&p1);
    *reinterpret_cast<uint2*>(g_x + (size_t)n * DHID + qc) = pk;
}

// ---------------------------------------------------------------------------
// Init histogram
// ---------------------------------------------------------------------------
__global__ void rgcn_init_kernel()
{
    int i = blockIdx.x * blockDim.x + threadIdx.x;
    if (i < NBKT_N) g_hist[i] = 0u;
}

__global__ void rgcn_hist_kernel(const int* __restrict__ dst, int n_edges)
{
    int e = blockIdx.x * blockDim.x + threadIdx.x;
    if (e >= n_edges) return;
    atomicAdd(&g_hist[(unsigned)dst[e]], 1u);
}

__global__ __launch_bounds__(1024) void rgcn_scan_local()
{
    __shared__ uint32_t sh[1024];
    int t = threadIdx.x;
    int i = blockIdx.x * 1024 + t;
    uint32_t v = g_hist[i];
    sh[t] = v;
    __syncthreads();
    #pragma unroll
    for (int off = 1; off < 1024; off <<= 1) {
        uint32_t u = (t >= off) ? sh[t - off] : 0u;
        __syncthreads();
        sh[t] += u;
        __syncthreads();
    }
    g_hist[i] = sh[t] - v;
    if (t == 1023) g_bsum[blockIdx.x] = sh[t];
}

__global__ __launch_bounds__(128) void rgcn_scan_bsums()
{
    __shared__ uint32_t sh[128];
    int t = threadIdx.x;
    uint32_t v = (t < NSCAN_BLK) ? g_bsum[t] : 0u;
    sh[t] = v;
    __syncthreads();
    #pragma unroll
    for (int off = 1; off < 128; off <<= 1) {
        uint32_t u = (t >= off) ? sh[t - off] : 0u;
        __syncthreads();
        sh[t] += u;
        __syncthreads();
    }
    g_bsum[t] = sh[t] - v;
}

__global__ __launch_bounds__(1024) void rgcn_scan_add()
{
    int i = blockIdx.x * 1024 + threadIdx.x;
    g_hist[i] += g_bsum[blockIdx.x];
}

__global__ void rgcn_scatter_kernel(
    const int*   __restrict__ r,
    const float* __restrict__ norm,
    const int*   __restrict__ src,
    const int*   __restrict__ dst,
    int n_edges)
{
    int e = blockIdx.x * blockDim.x + threadIdx.x;
    if (e >= n_edges) return;
    uint32_t pos = atomicAdd(&g_hist[(unsigned)dst[e]], 1u);
    uint2 ed;
    ed.x = (unsigned)src[e] | ((unsigned)r[e] << 20);
    ed.y = __float_as_uint(norm[e]);
    g_edges2[pos] = ed;
}

// ---------------------------------------------------------------------------
// Edge aggregate: one warp per DST node. y_b[d] = (1/deg) * sum_e (nm*c_b)*x[src]
// Gathers only the 256B raw x row per edge; accumulates 4 bases in registers.
// ---------------------------------------------------------------------------
__global__ __launch_bounds__(256) void rgcn_edge_agg(
    const float* __restrict__ w_comp,
    int n_nodes)
{
    int d    = blockIdx.x * 8 + (threadIdx.x >> 5);
    int lane = threadIdx.x & 31;
    if (d >= n_nodes) return;

    uint32_t end   = __ldg(&g_hist[d]);
    uint32_t begin = (d > 0) ? __ldg(&g_hist[d - 1]) : 0u;

    float acc0x = 0.f, acc0y = 0.f, acc0z = 0.f, acc0w = 0.f;
    float acc1x = 0.f, acc1y = 0.f, acc1z = 0.f, acc1w = 0.f;
    float acc2x = 0.f, acc2y = 0.f, acc2z = 0.f, acc2w = 0.f;
    float acc3x = 0.f, acc3y = 0.f, acc3z = 0.f, acc3w = 0.f;

    for (uint32_t e = begin; e < end; ++e) {
        uint2 ed = __ldg(&g_edges2[e]);
        int   s   = (int)(ed.x & 0xFFFFFu);
        int   rel = (int)(ed.x >> 20);
        float nm  = __uint_as_float(ed.y);
        float4 c  = __ldg(reinterpret_cast<const float4*>(w_comp) + rel);
        float c0 = nm * c.x, c1 = nm * c.y, c2 = nm * c.z, c3 = nm * c.w;

        uint2 q = __ldg(reinterpret_cast<const uint2*>(g_x + (size_t)s * DHID) + lane);
        float2 x01 = __half22float2(*reinterpret_cast<__half2*>(&q.x));
        float2 x23 = __half22float2(*reinterpret_cast<__half2*>(&q.y));

        acc0x += c0 * x01.x; acc0y += c0 * x01.y; acc0z += c0 * x23.x; acc0w += c0 * x23.y;
        acc1x += c1 * x01.x; acc1y += c1 * x01.y; acc1z += c1 * x23.x; acc1w += c1 * x23.y;
        acc2x += c2 * x01.x; acc2y += c2 * x01.y; acc2z += c2 * x23.x; acc2w += c2 * x23.y;
        acc3x += c3 * x01.x; acc3y += c3 * x01.y; acc3z += c3 * x23.x; acc3w += c3 * x23.y;
    }

    uint32_t deg = end - begin;
    float rc = (deg > 0u) ? (1.0f / (float)deg) : 1.0f;

    __half* yrow = g_y + (size_t)d * (NB * DHID) + lane * 4;
    {
        __half2 p0 = __floats2half2_rn(acc0x * rc, acc0y * rc);
        __half2 p1 = __floats2half2_rn(acc0z * rc, acc0w * rc);
        uint2 pk = {*reinterpret_cast<uint32_t*>(&p0), *reinterpret_cast<uint32_t*>(&p1)};
        *reinterpret_cast<uint2*>(yrow) = pk;
    }
    {
        __half2 p0 = __floats2half2_rn(acc1x * rc, acc1y * rc);
        __half2 p1 = __floats2half2_rn(acc1z * rc, acc1w * rc);
        uint2 pk = {*reinterpret_cast<uint32_t*>(&p0), *reinterpret_cast<uint32_t*>(&p1)};
        *reinterpret_cast<uint2*>(yrow + DHID) = pk;
    }
    {
        __half2 p0 = __floats2half2_rn(acc2x * rc, acc2y * rc);
        __half2 p1 = __floats2half2_rn(acc2z * rc, acc2w * rc);
        uint2 pk = {*reinterpret_cast<uint32_t*>(&p0), *reinterpret_cast<uint32_t*>(&p1)};
        *reinterpret_cast<uint2*>(yrow + 2 * DHID) = pk;
    }
    {
        __half2 p0 = __floats2half2_rn(acc3x * rc, acc3y * rc);
        __half2 p1 = __floats2half2_rn(acc3z * rc, acc3w * rc);
        uint2 pk = {*reinterpret_cast<uint32_t*>(&p0), *reinterpret_cast<uint32_t*>(&p1)};
        *reinterpret_cast<uint2*>(yrow + 3 * DHID) = pk;
    }
}

// ---------------------------------------------------------------------------
// GEMM2: out[d][o] = y[d][0:512] @ Wt[o][0:512] + bias[o]
// Block: 128 rows x 128 cols, K=512 in 4 chunks. HMMA m16n8k16, 8 warps.
// ---------------------------------------------------------------------------
__device__ __forceinline__ uint32_t smem_u32(const void* p) {
    uint32_t a;
    asm("{ .reg .u64 t; cvta.to.shared.u64 t, %1; cvt.u32.u64 %0, t; }" : "=r"(a) : "l"(p));
    return a;
}
__device__ __forceinline__ void ldsm_x4(uint32_t* r, uint32_t addr) {
    asm volatile("ldmatrix.sync.aligned.m8n8.x4.shared.b16 {%0,%1,%2,%3}, [%4];"
                 : "=r"(r[0]), "=r"(r[1]), "=r"(r[2]), "=r"(r[3]) : "r"(addr));
}
__device__ __forceinline__ void ldsm_x2(uint32_t* r, uint32_t addr) {
    asm volatile("ldmatrix.sync.aligned.m8n8.x2.shared.b16 {%0,%1}, [%2];"
                 : "=r"(r[0]), "=r"(r[1]) : "r"(addr));
}
__device__ __forceinline__ void mma16816(float* c, const uint32_t* a, const uint32_t* b) {
    asm volatile(
        "mma.sync.aligned.m16n8k16.row.col.f32.f16.f16.f32 "
        "{%0,%1,%2,%3}, {%4,%5,%6,%7}, {%8,%9}, {%0,%1,%2,%3};"
        : "+f"(c[0]), "+f"(c[1]), "+f"(c[2]), "+f"(c[3])
        : "r"(a[0]), "r"(a[1]), "r"(a[2]), "r"(a[3]), "r"(b[0]), "r"(b[1]));
}

#define SMEM_BYTES ((128 * KP * 2) * 2)

__global__ __launch_bounds__(256) void rgcn_gemm2(
    const float* __restrict__ bias,
    float*       __restrict__ out,
    int n_nodes)
{
    extern __shared__ __align__(16) __half smem[];
    __half* As = smem;              // [128][KP], k-chunk of y
    __half* Bs = smem + 128 * KP;   // [128][KP], k-chunk of Wt (rows = o)

    const int tid  = threadIdx.x;
    const int lane = tid & 31;
    const int wrp  = tid >> 5;
    const int wm   = (wrp & 3) * 32;
    const int wn   = (wrp >> 2) * 64;
    const int m0   = blockIdx.x * 128;

    uint32_t as_base = smem_u32(As);
    uint32_t bs_base = smem_u32(Bs);
    const int arow  = (lane & 15);
    const int acol8 = 8 * (lane >> 4);
    const int brow  = (lane & 7);
    const int bcol8 = 8 * ((lane >> 3) & 1);
    const int gq = lane >> 2;
    const int tg = lane & 3;

    float acc[2][8][4];
    #pragma unroll
    for (int mi = 0; mi < 2; ++mi)
        #pragma unroll
        for (int ni = 0; ni < 8; ++ni)
            #pragma unroll
            for (int q = 0; q < 4; ++q) acc[mi][ni][q] = 0.f;

    for (int kc = 0; kc < 4; ++kc) {
        __syncthreads();
        // A chunk: y[m0+m][kc*128 + k]
        #pragma unroll
        for (int it = 0; it < 8; ++it) {
            int idx = it * 256 + tid;      // 2048 = 128 rows x 16 uint4
            int m   = idx >> 4;
            int kq  = (idx & 15) * 8;
            int row = m0 + m;
            uint4 v = make_uint4(0u, 0u, 0u, 0u);
            if (row < n_nodes)
                v = *reinterpret_cast<const uint4*>(g_y + (size_t)row * (NB * DHID) + kc * DHID + kq);
            *reinterpret_cast<uint4*>(As + m * KP + kq) = v;
        }
        // B chunk: Wt[o][kc*128 + k]
        #pragma unroll
        for (int it = 0; it < 8; ++it) {
            int idx = it * 256 + tid;
            int o   = idx >> 4;
            int kq  = (idx & 15) * 8;
            *reinterpret_cast<uint4*>(Bs + o * KP + kq) =
                *reinterpret_cast<const uint4*>(g_wt2 + o * (NB * DHID) + kc * DHID + kq);
        }
        __syncthreads();

        #pragma unroll
        for (int kk = 0; kk < 8; ++kk) {
            uint32_t af[2][4], bf[8][2];
            #pragma unroll
            for (int mi = 0; mi < 2; ++mi)
                ldsm_x4(af[mi], as_base + ((wm + mi * 16 + arow) * KP + kk * 16 + acol8) * 2);
            #pragma unroll
            for (int ni = 0; ni < 8; ++ni)
                ldsm_x2(bf[ni], bs_base + ((wn + ni * 8 + brow) * KP + kk * 16 + bcol8) * 2);
            #pragma unroll
            for (int mi = 0; mi < 2; ++mi)
                #pragma unroll
                for (int ni = 0; ni < 8; ++ni)
                    mma16816(acc[mi][ni], af[mi], bf[ni]);
        }
    }

    // Epilogue: out = acc + bias (fp32)
    #pragma unroll
    for (int mi = 0; mi < 2; ++mi) {
        #pragma unroll
        for (int half_ = 0; half_ < 2; ++half_) {
            int row = m0 + wm + mi * 16 + gq + half_ * 8;
            if (row < n_nodes) {
                #pragma unroll
                for (int ni = 0; ni < 8; ++ni) {
                    int col = wn + ni * 8 + tg * 2;
                    float2 bv = __ldg(reinterpret_cast<const float2*>(bias) + (col >> 1));
                    float2 o;
                    o.x = acc[mi][ni][half_ * 2]     + bv.x;
                    o.y = acc[mi][ni][half_ * 2 + 1] + bv.y;
                    *reinterpret_cast<float2*>(out + (size_t)row * DHID + col) = o;
                }
            }
        }
    }
}

// ---------------------------------------------------------------------------
// Inputs: h, r, norm, src, dst, emb_table, weight, w_comp, h_bias
// ---------------------------------------------------------------------------
extern "C" void kernel_launch(void* const* d_in, const int* in_sizes, int n_in,
                              void* d_out, int out_size)
{
    const int*   h      = (const int*)  d_in[0];
    const int*   r      = (const int*)  d_in[1];
    const float* norm   = (const float*)d_in[2];
    const int*   src    = (const int*)  d_in[3];
    const int*   dst    = (const int*)  d_in[4];
    const float* emb    = (const float*)d_in[5];
    const float* weight = (const float*)d_in[6];
    const float* w_comp = (const float*)d_in[7];
    const float* bias   = (const float*)d_in[8];

    int n_nodes = in_sizes[0];
    int n_edges = in_sizes[1];
    float* out = (float*)d_out;

    cudaFuncSetAttribute(rgcn_gemm2, cudaFuncAttributeMaxDynamicSharedMemorySize, SMEM_BYTES);

    // 0) preps
    rgcn_prep_w<<<(NB * DHID * DHID + 255) / 256, 256>>>(weight);
    rgcn_prep_x<<<(n_nodes * 32 + 255) / 256, 256>>>(h, emb, n_nodes);
    rgcn_init_kernel<<<(NBKT_N + 255) / 256, 256>>>();

    // 1) counting sort of edges by dst node
    int eblk = (n_edges + 255) / 256;
    rgcn_hist_kernel<<<eblk, 256>>>(dst, n_edges);
    rgcn_scan_local<<<NSCAN_BLK, 1024>>>();
    rgcn_scan_bsums<<<1, 128>>>();
    rgcn_scan_add<<<NSCAN_BLK, 1024>>>();
    rgcn_scatter_kernel<<<eblk, 256>>>(r, norm, src, dst, n_edges);

    // 2) per-dst raw-feature aggregation (y, deg-scaled)
    rgcn_edge_agg<<<(n_nodes + 7) / 8, 256>>>(w_comp, n_nodes);

    // 3) projection GEMM + bias -> out
    rgcn_gemm2<<<(n_nodes + 127) / 128, 256, SMEM_BYTES>>>(bias, out, n_nodes);
}